// round 15
// baseline (speedup 1.0000x reference)
#include <cuda_runtime.h>
#include <cuda_fp16.h>
#include <math.h>
#include <stdint.h>

// Problem constants (Gemma2 attention layer)
#define B_ 4
#define S_ 2048
#define H_ 2048
#define NH_ 8
#define NKV_ 4
#define HD_ 256
#define WIN_ 1024
#define SCALE_ 0.0625f   // 256^-0.5

#define GK_   2048       // inner K of every GEMM
#define KC    64         // K-chunk per pipeline stage
#define NC    32         // GK_ / KC
#define NSTAGE 3
#define STGB  16384      // bytes per operand stage (128 rows x 128B, packed)

// ---------------------------------------------------------------------------
// Scratch (device globals — no allocation allowed)
// ---------------------------------------------------------------------------
__device__ __half g_qkvh[(size_t)B_ * S_ * 4096];             // fp16 Q|K|V (64 MB)
__device__ float g_bias4[4096];
__device__ __half g_a2[(size_t)B_ * S_ * GK_];                // 32 MB (single fp16)
__device__ __half g_w2[(size_t)4096 * GK_];                   // 16 MB (single fp16)
__device__ float2 g_rope[(size_t)B_ * S_ * 128];              // cos/sin table
// attention operands
__device__ __half g_q2[(size_t)B_ * NH_ * S_ * 256];          // [b][h][s][q(256)]
__device__ __half g_k2[(size_t)B_ * NKV_ * S_ * 256];         // [b][kvh][s][k(256)]
__device__ __half g_vt[(size_t)B_ * NKV_ * 256 * S_];         // [b][kvh][d(256)][s]

// ---------------------------------------------------------------------------
// Helpers
// ---------------------------------------------------------------------------
__device__ __forceinline__ uint32_t smem_u32(const void* p) {
    uint32_t a;
    asm("{ .reg .u64 t; cvta.to.shared.u64 t, %1; cvt.u32.u64 %0, t; }" : "=r"(a) : "l"(p));
    return a;
}
__device__ __forceinline__ void cp16(uint32_t dst, const void* src) {
    asm volatile("cp.async.cg.shared.global [%0], [%1], 16;" :: "r"(dst), "l"(src));
}
#define CP_COMMIT() asm volatile("cp.async.commit_group;" ::: "memory")
#define CP_WAIT1()  asm volatile("cp.async.wait_group 1;" ::: "memory")
#define CP_WAIT2()  asm volatile("cp.async.wait_group 2;" ::: "memory")

__device__ __forceinline__ void mma16816(float* c, const uint32_t* a, const uint32_t* b) {
    asm volatile(
        "mma.sync.aligned.m16n8k16.row.col.f32.f16.f16.f32 "
        "{%0,%1,%2,%3}, {%4,%5,%6,%7}, {%8,%9}, {%0,%1,%2,%3};"
        : "+f"(c[0]), "+f"(c[1]), "+f"(c[2]), "+f"(c[3])
        : "r"(a[0]), "r"(a[1]), "r"(a[2]), "r"(a[3]), "r"(b[0]), "r"(b[1]));
}
#define LDSM4(r, a)                                                             \
    asm volatile("ldmatrix.sync.aligned.m8n8.x4.shared.b16 {%0,%1,%2,%3}, [%4];" \
        : "=r"((r)[0]), "=r"((r)[1]), "=r"((r)[2]), "=r"((r)[3]) : "r"(a))

// ---------------------------------------------------------------------------
// RoPE table + bias concat (Q|K|V)
// ---------------------------------------------------------------------------
__global__ __launch_bounds__(256) void rope_table(const int* __restrict__ positions,
                                                  float2* __restrict__ T)
{
    int idx = blockIdx.x * 256 + threadIdx.x;     // B*S*128
    int d = idx & 127;
    int bs = idx >> 7;
    int pos = positions[bs];
    float inv_freq = exp2f(-(float)d * 0.103810253f);
    float fr = (float)pos * inv_freq;
    float sn, cs;
    sincosf(fr, &sn, &cs);
    T[idx] = make_float2(cs, sn);
}

__global__ __launch_bounds__(256) void bias_concat(const float* __restrict__ bq,
                                                   const float* __restrict__ bk,
                                                   const float* __restrict__ bv,
                                                   float* __restrict__ dst)
{
    int i = blockIdx.x * 256 + threadIdx.x;       // 4096
    float v;
    if (i < 2048) v = bq[i];
    else if (i < 3072) v = bk[i - 2048];
    else v = bv[i - 3072];
    dst[i] = v;
}

// ---------------------------------------------------------------------------
// Conversions for GEMM
// ---------------------------------------------------------------------------
__global__ __launch_bounds__(256) void convA2(const float* __restrict__ A,
                                              __half* __restrict__ A2)
{
    int idx = blockIdx.x * 256 + threadIdx.x;
    int m = idx >> 9;
    int j = (idx & 511) * 4;
    float4 v = *(const float4*)(A + (size_t)m * GK_ + j);
    __half h[4] = {__float2half_rn(v.x), __float2half_rn(v.y),
                   __float2half_rn(v.z), __float2half_rn(v.w)};
    *(uint2*)&A2[(size_t)m * GK_ + j] = *(uint2*)h;
}

__global__ __launch_bounds__(256) void convW2(const float* __restrict__ W,
                                              __half* __restrict__ W2, int N)
{
    __shared__ float t[32][33];
    int n0 = blockIdx.x * 32, k0 = blockIdx.y * 32;
    int tx = threadIdx.x & 31, ty = threadIdx.x >> 5;
#pragma unroll
    for (int i = 0; i < 32; i += 8)
        t[ty + i][tx] = W[(size_t)(k0 + ty + i) * N + n0 + tx];
    __syncthreads();
#pragma unroll
    for (int i = 0; i < 32; i += 8) {
        int n = n0 + ty + i, k = k0 + tx;
        W2[(size_t)n * GK_ + k] = __float2half_rn(t[tx][ty + i]);
    }
}

// ---------------------------------------------------------------------------
// mma.sync fp16 GEMM: C = A2[8192,2048] @ W2[Nn,2048]^T + bias.
// Output: fp32 (C) when Ch==nullptr, else fp16 (Ch).
// 128 threads (4 warps, 2m x 2n), warp tile 64x64; packed swizzled stages,
// 2 CTAs/SM.
// ---------------------------------------------------------------------------
__global__ __launch_bounds__(128, 2) void gemm_mma(
    const __half* __restrict__ A2, const __half* __restrict__ B2,
    const float* __restrict__ bias, float* __restrict__ C,
    __half* __restrict__ Ch, int Nn)
{
    extern __shared__ __align__(16) char smraw[];
    const uint32_t sAu = smem_u32(smraw);                  // 3 stages x 16KB
    const uint32_t sBu = sAu + NSTAGE * STGB;              // 3 stages x 16KB
    float* sbias = (float*)(smraw + 2 * NSTAGE * STGB);    // [128]

    const int tid = threadIdx.x;
    const int m0 = blockIdx.y * 128;
    const int n0 = blockIdx.x * 128;

    sbias[tid] = bias ? bias[n0 + tid] : 0.f;

    const int seg = tid & 7;
    const int r0  = tid >> 3;                              // 0..15
    const uint32_t stOff = (uint32_t)(r0 * 128) + (uint32_t)(((seg ^ (r0 & 7)) & 7) << 4);
    const __half* Ag = A2 + (size_t)m0 * GK_ + seg * 8;
    const __half* Bg = B2 + (size_t)n0 * GK_ + seg * 8;

#define LOAD_STAGE(chunk, st) do {                                              \
    int _k0 = (chunk) * KC;                                                     \
    uint32_t _da = sAu + (uint32_t)(st) * STGB + stOff;                         \
    uint32_t _db = sBu + (uint32_t)(st) * STGB + stOff;                         \
    _Pragma("unroll")                                                           \
    for (int _rr = 0; _rr < 8; _rr++) {                                         \
        int _row = r0 + _rr * 16;                                               \
        cp16(_da + _rr * 2048u, Ag + (size_t)_row * GK_ + _k0);                 \
        cp16(_db + _rr * 2048u, Bg + (size_t)_row * GK_ + _k0);                 \
    }                                                                           \
} while (0)

    const int wid = tid >> 5, lane = tid & 31;
    const int wm = (wid >> 1) * 64;
    const int wn = (wid & 1) * 64;
    const int g = lane >> 2, t = lane & 3;

    const int hiA = lane >> 4;
    const int maskA = lane & 7;
    const uint32_t aByte = (uint32_t)((wm + (lane & 15)) * 128);
    const int hiB = (lane >> 3) & 1;
    const int maskB = lane & 7;
    const uint32_t bByte = (uint32_t)((wn + ((lane >> 4) << 3) + (lane & 7)) * 128);

    float acc[4][8][4];
#pragma unroll
    for (int mi = 0; mi < 4; mi++)
#pragma unroll
        for (int ni = 0; ni < 8; ni++)
#pragma unroll
            for (int e = 0; e < 4; e++) acc[mi][ni][e] = 0.f;

    LOAD_STAGE(0, 0); CP_COMMIT();
    LOAD_STAGE(1, 1); CP_COMMIT();

    for (int c = 0; c < NC; c++) {
        CP_WAIT1();
        __syncthreads();

        int lc = c + 2;
        int st_ld = lc - (lc / 3) * 3;
        if (lc < NC) LOAD_STAGE(lc, st_ld);
        CP_COMMIT();

        int st = c - (c / 3) * 3;
        const uint32_t aS = sAu + st * STGB + aByte;
        const uint32_t bS = sBu + st * STGB + bByte;

#pragma unroll
        for (int ks = 0; ks < 4; ks++) {
            const uint32_t offA = (uint32_t)(((2 * ks + hiA) ^ maskA) << 4);
            const uint32_t offB = (uint32_t)(((2 * ks + hiB) ^ maskB) << 4);
            uint32_t af[4][4], bq4[4][4];
#pragma unroll
            for (int mi = 0; mi < 4; mi++) LDSM4(af[mi], aS + mi * 2048u + offA);
#pragma unroll
            for (int p = 0; p < 4; p++) LDSM4(bq4[p], bS + p * 2048u + offB);
#pragma unroll
            for (int mi = 0; mi < 4; mi++)
#pragma unroll
                for (int ni = 0; ni < 8; ni++)
                    mma16816(acc[mi][ni], af[mi], &bq4[ni >> 1][(ni & 1) * 2]);
        }
    }

    __syncthreads();
    if (Ch) {
#pragma unroll
        for (int mi = 0; mi < 4; mi++) {
            int row = m0 + wm + mi * 16 + g;
#pragma unroll
            for (int ni = 0; ni < 8; ni++) {
                int lcol = wn + ni * 8 + 2 * t;
                float b0 = sbias[lcol], b1 = sbias[lcol + 1];
                __half2 v0 = __floats2half2_rn(acc[mi][ni][0] + b0, acc[mi][ni][1] + b1);
                __half2 v1 = __floats2half2_rn(acc[mi][ni][2] + b0, acc[mi][ni][3] + b1);
                *(__half2*)(Ch + (size_t)row * Nn + n0 + lcol) = v0;
                *(__half2*)(Ch + (size_t)(row + 8) * Nn + n0 + lcol) = v1;
            }
        }
    } else {
#pragma unroll
        for (int mi = 0; mi < 4; mi++) {
            int row = m0 + wm + mi * 16 + g;
#pragma unroll
            for (int ni = 0; ni < 8; ni++) {
                int lcol = wn + ni * 8 + 2 * t;
                float b0 = sbias[lcol], b1 = sbias[lcol + 1];
                float2 v0 = {acc[mi][ni][0] + b0, acc[mi][ni][1] + b1};
                float2 v1 = {acc[mi][ni][2] + b0, acc[mi][ni][3] + b1};
                *(float2*)(C + (size_t)row * Nn + n0 + lcol) = v0;
                *(float2*)(C + (size_t)(row + 8) * Nn + n0 + lcol) = v1;
            }
        }
    }
#undef LOAD_STAGE
}

// ---------------------------------------------------------------------------
// Fused RoPE (table) + scale + fp16 conversion for Q and K (fp16 input).
// ---------------------------------------------------------------------------
__global__ __launch_bounds__(256) void conv_qk(
    const __half* __restrict__ qkv, const float2* __restrict__ T,
    __half* __restrict__ Q2, __half* __restrict__ K2)
{
    int idx = blockIdx.x * 256 + threadIdx.x;   // 4*2048*12*32
    int dg = idx & 31;
    int r = idx >> 5;
    int head = r % 12;
    int bs = r / 12;
    int b = bs >> 11, s = bs & 2047;
    int d0 = dg * 4;

    const bool isq = head < NH_;
    const __half* src = qkv + (size_t)bs * 4096 + head * HD_;
    const float sc = isq ? SCALE_ : 1.0f;

    __half x1[4], x2[4];
    *(uint2*)x1 = *(const uint2*)(src + d0);
    *(uint2*)x2 = *(const uint2*)(src + d0 + 128);
    __half h1[4], h2[4];
#pragma unroll
    for (int e = 0; e < 4; e++) {
        float2 cssn = T[(size_t)bs * 128 + d0 + e];
        float a1 = __half2float(x1[e]);
        float a2 = __half2float(x2[e]);
        float y1 = (a1 * cssn.x - a2 * cssn.y) * sc;
        float y2 = (a2 * cssn.x + a1 * cssn.y) * sc;
        h1[e] = __float2half_rn(y1);
        h2[e] = __float2half_rn(y2);
    }
    __half* dst = isq ? (Q2 + ((size_t)(b * NH_ + head) * S_ + s) * 256)
                      : (K2 + ((size_t)(b * NKV_ + head - NH_) * S_ + s) * 256);
    *(uint2*)(dst + d0)       = *(uint2*)h1;
    *(uint2*)(dst + 128 + d0) = *(uint2*)h2;
}

// ---------------------------------------------------------------------------
// V transpose: qkv cols [3072,4096) (fp16) -> g_vt [b][kvh][256][S]
// (pass-through values; fp16->fp16 exact)
// ---------------------------------------------------------------------------
__global__ __launch_bounds__(256) void conv_v(const __half* __restrict__ qkv,
                                              __half* __restrict__ Vt)
{
    __shared__ __half tile[32][40];
    int s0 = blockIdx.x * 32, d0 = blockIdx.y * 32;
    int b = blockIdx.z >> 2, kvh = blockIdx.z & 3;
    int tx = threadIdx.x & 31, ty = threadIdx.x >> 5;
#pragma unroll
    for (int i = 0; i < 32; i += 8)
        tile[ty + i][tx] = qkv[(size_t)(b * S_ + s0 + ty + i) * 4096 + 3072 + kvh * HD_ + d0 + tx];
    __syncthreads();
    size_t base = (size_t)(b * NKV_ + kvh) * 256;
#pragma unroll
    for (int i = 0; i < 32; i += 8) {
        int d = d0 + ty + i;
        Vt[(base + d) * S_ + s0 + tx] = tile[tx][ty + i];
    }
}

// ---------------------------------------------------------------------------
// Tensor-core sliding-window flash attention (fp16). (unchanged from R14)
// q-tile 128, kv-tile 64, double-buffered K+V, Q frags hoisted, PV single.
// ---------------------------------------------------------------------------
#define QROWB 512    // bytes per Q/K smem row (256 halfs, packed)
#define VLD 72       // fp16 elems per V smem row (64 + 8 pad), 144B
#define KSTG 32768   // bytes per K stage (64 x 512)
#define VSTG 36864   // bytes per V stage (256 x 144)

__global__ __launch_bounds__(256, 1) void attn_mma(
    const __half* __restrict__ Q2, const __half* __restrict__ K2,
    const __half* __restrict__ Vt, __half* __restrict__ A2out)
{
    extern __shared__ __align__(16) __half smb[];
    const uint32_t QsA = smem_u32(smb);                  // 128 x 512B = 64KB
    const uint32_t KsA = QsA + 128 * QROWB;              // 2 x 32KB
    const uint32_t VsA = KsA + 2 * KSTG;                 // 2 x 36KB  -> total 200KB

    const int tid = threadIdx.x;
    const int w = tid >> 5, lane = tid & 31;
    const int g = lane >> 2, t = lane & 3;
    const int q0 = blockIdx.x * 128;
    const int h = blockIdx.y;
    const int b = blockIdx.z;
    const int kvh = h >> 1;

    const __half* Qg = Q2 + ((size_t)(b * NH_ + h) * S_ + q0) * 256;
    const __half* Kg = K2 + (size_t)(b * NKV_ + kvh) * S_ * 256;
    const __half* Vg = Vt + (size_t)(b * NKV_ + kvh) * 256 * S_;

    const int hiQ = lane >> 4;
    const int maskQ = lane & 7;
    const uint32_t qByte = QsA + (uint32_t)((w * 16 + (lane & 15)) * QROWB);
    const int hiK = (lane >> 3) & 1;
    const int maskK = lane & 7;
    const uint32_t kBase = KsA + (uint32_t)((((lane >> 4) << 3) + (lane & 7)) * QROWB);
    const uint32_t vBase = VsA + (uint32_t)((((lane >> 4) << 3) + (lane & 7)) * VLD * 2 +
                                            ((lane >> 3) & 1) * 16);

    // ---- load Q tile (group 0): 128 rows x 256 elems
#pragma unroll
    for (int it = 0; it < 16; it++) {
        int idx = tid + it * 256;
        int r = idx >> 5, seg = idx & 31;
        uint32_t d = QsA + (uint32_t)(r * QROWB) + (uint32_t)((seg ^ (r & 7)) << 4);
        cp16(d, Qg + (size_t)r * 256 + seg * 8);
    }
    CP_COMMIT();

    int lo = q0 - (WIN_ - 1); if (lo < 0) lo = 0;
    const int kt0 = (lo >> 6) << 6;
    const int ntiles = ((q0 + 64) - kt0) / 64 + 1;

#define LOAD_KV(kt, st) do {                                                    \
    _Pragma("unroll")                                                           \
    for (int _it = 0; _it < 8; _it++) {                                         \
        int _i = tid + _it * 256;                                               \
        int _r = _i >> 5, _sg = _i & 31;                                        \
        uint32_t _d = KsA + (uint32_t)(st) * KSTG + (uint32_t)(_r * QROWB) +     \
                      (uint32_t)((_sg ^ (_r & 7)) << 4);                         \
        cp16(_d, Kg + ((size_t)((kt) + _r)) * 256 + _sg * 8);                   \
    }                                                                           \
    _Pragma("unroll")                                                           \
    for (int _it = 0; _it < 8; _it++) {                                         \
        int _i = tid + _it * 256;                                               \
        int _r = _i >> 3, _sg = _i & 7;                                         \
        cp16(VsA + (uint32_t)(st) * VSTG + (uint32_t)(_r * VLD + _sg * 8) * 2,  \
             Vg + (size_t)_r * S_ + (kt) + _sg * 8);                            \
    }                                                                           \
} while (0)

    LOAD_KV(kt0, 0); CP_COMMIT();                 // group 1
    if (ntiles > 1) LOAD_KV(kt0 + 64, 1);
    CP_COMMIT();                                   // group 2 (possibly empty)

    // ---- hoist Q fragments: wait for group 0 only
    CP_WAIT2();
    __syncthreads();
    uint32_t qf[16][4];
#pragma unroll
    for (int ks = 0; ks < 16; ks++) {
        const uint32_t offQ = (uint32_t)(((2 * ks + hiQ) ^ maskQ) << 4);
        LDSM4(qf[ks], qByte + offQ);
    }

    float o[32][4];
#pragma unroll
    for (int nt = 0; nt < 32; nt++)
#pragma unroll
        for (int e = 0; e < 4; e++) o[nt][e] = 0.f;
    float rmax0 = -1e20f, rmax1 = -1e20f, rsum0 = 0.f, rsum1 = 0.f;

    const int rmin = q0 + w * 16;
    const int rmax_w = rmin + 15;
    const int row0 = rmin + g;
    const int row1 = row0 + 8;
    const int tcol = 2 * t;

    for (int j = 0; j < ntiles; j++) {
        const int kt = kt0 + 64 * j;
        const int st = j & 1;
        const bool skipT = (kt > rmax_w) || (kt + 63 < rmin - (WIN_ - 1));
        const bool edge = !((kt + 63 <= rmin) && (kt >= rmax_w - (WIN_ - 1)));

        CP_WAIT1();            // KV_j resident (pending: KV_{j+1})
        __syncthreads();

        if (!skipT) {
            const uint32_t kByte = kBase + st * KSTG;
            const uint32_t vB = vBase + st * VSTG;
            float s[8][4];
#pragma unroll
            for (int nt = 0; nt < 8; nt++)
#pragma unroll
                for (int e = 0; e < 4; e++) s[nt][e] = 0.f;
#pragma unroll 2
            for (int ks = 0; ks < 16; ks++) {
                const uint32_t offK = (uint32_t)(((2 * ks + hiK) ^ maskK) << 4);
                uint32_t bb[4][4];
#pragma unroll
                for (int r16 = 0; r16 < 4; r16++)
                    LDSM4(bb[r16], kByte + r16 * (16 * QROWB) + offK);
#pragma unroll
                for (int nt = 0; nt < 8; nt++)
                    mma16816(s[nt], qf[ks], &bb[nt >> 1][(nt & 1) * 2]);
            }
            if (edge) {
#pragma unroll
                for (int nt = 0; nt < 8; nt++) {
                    int c0 = kt + nt * 8 + tcol, c1 = c0 + 1;
                    if (!(c0 <= row0 && c0 > row0 - WIN_)) s[nt][0] = -1e30f;
                    if (!(c1 <= row0 && c1 > row0 - WIN_)) s[nt][1] = -1e30f;
                    if (!(c0 <= row1 && c0 > row1 - WIN_)) s[nt][2] = -1e30f;
                    if (!(c1 <= row1 && c1 > row1 - WIN_)) s[nt][3] = -1e30f;
                }
            }
            float m0 = -1e30f, m1 = -1e30f;
#pragma unroll
            for (int nt = 0; nt < 8; nt++) {
                m0 = fmaxf(m0, fmaxf(s[nt][0], s[nt][1]));
                m1 = fmaxf(m1, fmaxf(s[nt][2], s[nt][3]));
            }
            m0 = fmaxf(m0, __shfl_xor_sync(0xffffffffu, m0, 1));
            m0 = fmaxf(m0, __shfl_xor_sync(0xffffffffu, m0, 2));
            m1 = fmaxf(m1, __shfl_xor_sync(0xffffffffu, m1, 1));
            m1 = fmaxf(m1, __shfl_xor_sync(0xffffffffu, m1, 2));
            float nm0 = fmaxf(rmax0, m0), nm1 = fmaxf(rmax1, m1);
            float al0 = __expf(rmax0 - nm0), al1 = __expf(rmax1 - nm1);
            float ls0 = 0.f, ls1 = 0.f;
#pragma unroll
            for (int nt = 0; nt < 8; nt++) {
                s[nt][0] = __expf(s[nt][0] - nm0);
                s[nt][1] = __expf(s[nt][1] - nm0);
                s[nt][2] = __expf(s[nt][2] - nm1);
                s[nt][3] = __expf(s[nt][3] - nm1);
                ls0 += s[nt][0] + s[nt][1];
                ls1 += s[nt][2] + s[nt][3];
            }
            ls0 += __shfl_xor_sync(0xffffffffu, ls0, 1);
            ls0 += __shfl_xor_sync(0xffffffffu, ls0, 2);
            ls1 += __shfl_xor_sync(0xffffffffu, ls1, 1);
            ls1 += __shfl_xor_sync(0xffffffffu, ls1, 2);
            rsum0 = rsum0 * al0 + ls0;
            rsum1 = rsum1 * al1 + ls1;
            rmax0 = nm0; rmax1 = nm1;
#pragma unroll
            for (int nt = 0; nt < 32; nt++) {
                o[nt][0] *= al0; o[nt][1] *= al0;
                o[nt][2] *= al1; o[nt][3] *= al1;
            }
            // PV: 4 key-chunks of 16; pack P fragments on the fly
#pragma unroll
            for (int kk = 0; kk < 4; kk++) {
                __half2 h01a = __floats2half2_rn(s[2 * kk][0], s[2 * kk][1]);
                __half2 h23a = __floats2half2_rn(s[2 * kk][2], s[2 * kk][3]);
                __half2 h01b = __floats2half2_rn(s[2 * kk + 1][0], s[2 * kk + 1][1]);
                __half2 h23b = __floats2half2_rn(s[2 * kk + 1][2], s[2 * kk + 1][3]);
                uint32_t Ah[4] = {*(uint32_t*)&h01a, *(uint32_t*)&h23a,
                                  *(uint32_t*)&h01b, *(uint32_t*)&h23b};
#pragma unroll
                for (int p = 0; p < 16; p++) {
                    uint32_t rv[4];
                    LDSM4(rv, vB + p * (16 * VLD * 2) + kk * 32);
                    mma16816(o[2 * p], Ah, &rv[0]);
                    mma16816(o[2 * p + 1], Ah, &rv[2]);
                }
            }
        }
        __syncthreads();       // all warps done with stage st
        int lj = j + 2;
        if (lj < ntiles) LOAD_KV(kt0 + 64 * lj, lj & 1);
        CP_COMMIT();           // always commit to keep group count uniform
    }

    // epilogue: normalize and write fp16 directly into A2
    float inv0 = 1.0f / rsum0, inv1 = 1.0f / rsum1;
    __half* d0p = A2out + (size_t)(b * S_ + row0) * GK_ + h * HD_;
    __half* d1p = A2out + (size_t)(b * S_ + row1) * GK_ + h * HD_;
#pragma unroll
    for (int nt = 0; nt < 32; nt++) {
        int d = nt * 8 + tcol;
        __half2 v0 = __floats2half2_rn(o[nt][0] * inv0, o[nt][1] * inv0);
        __half2 v1 = __floats2half2_rn(o[nt][2] * inv1, o[nt][3] * inv1);
        *(__half2*)(d0p + d) = v0;
        *(__half2*)(d1p + d) = v1;
    }
#undef LOAD_KV
}

// ---------------------------------------------------------------------------
// Launch
// ---------------------------------------------------------------------------
extern "C" void kernel_launch(void* const* d_in, const int* in_sizes, int n_in,
                              void* d_out, int out_size)
{
    const float* hidden    = (const float*)d_in[0];
    const int*   positions = (const int*)d_in[1];
    const float* Wq        = (const float*)d_in[2];
    const float* bq        = (const float*)d_in[3];
    const float* Wk        = (const float*)d_in[4];
    const float* bk        = (const float*)d_in[5];
    const float* Wv        = (const float*)d_in[6];
    const float* bv        = (const float*)d_in[7];
    const float* Wo        = (const float*)d_in[8];
    float* out = (float*)d_out;

    float* b4;
    float2* rt;
    __half *qkvh, *a2, *w2, *q2, *k2, *vt;
    cudaGetSymbolAddress((void**)&qkvh, g_qkvh);
    cudaGetSymbolAddress((void**)&b4, g_bias4);
    cudaGetSymbolAddress((void**)&a2, g_a2);
    cudaGetSymbolAddress((void**)&w2, g_w2);
    cudaGetSymbolAddress((void**)&rt, g_rope);
    cudaGetSymbolAddress((void**)&q2, g_q2);
    cudaGetSymbolAddress((void**)&k2, g_k2);
    cudaGetSymbolAddress((void**)&vt, g_vt);

    const int M = B_ * S_;
    const size_t gemm_smem = (size_t)2 * NSTAGE * STGB + 512;   // 98,816 B
    cudaFuncSetAttribute(gemm_mma, cudaFuncAttributeMaxDynamicSharedMemorySize, (int)gemm_smem);

    rope_table<<<(B_ * S_ * 128) / 256, 256>>>(positions, rt);
    bias_concat<<<4096 / 256, 256>>>(bq, bk, bv, b4);
    convA2<<<M * 512 / 256, 256>>>(hidden, a2);

    // merged Q|K|V projection (N=4096), fp16 output
    convW2<<<dim3(2048 / 32, 64), 256>>>(Wq, w2, 2048);
    convW2<<<dim3(1024 / 32, 64), 256>>>(Wk, w2 + (size_t)2048 * GK_, 1024);
    convW2<<<dim3(1024 / 32, 64), 256>>>(Wv, w2 + (size_t)3072 * GK_, 1024);
    gemm_mma<<<dim3(32, 64), 128, gemm_smem>>>(a2, w2, b4, nullptr, qkvh, 4096);

    conv_qk<<<(B_ * S_ * 12 * 32) / 256, 256>>>(qkvh, rt, q2, k2);
    conv_v<<<dim3(S_ / 32, HD_ / 32, B_ * NKV_), 256>>>(qkvh, vt);

    // attention writes fp16 directly into A2
    {
        size_t smem = (size_t)(128 * QROWB + 2 * KSTG + 2 * VSTG);  // 204,800 B
        cudaFuncSetAttribute(attn_mma, cudaFuncAttributeMaxDynamicSharedMemorySize, (int)smem);
        attn_mma<<<dim3(S_ / 128, NH_, B_), 256, smem>>>(q2, k2, vt, a2);
    }

    // O projection (fp32 output to harness buffer)
    convW2<<<dim3(2048 / 32, 64), 256>>>(Wo, w2, 2048);
    gemm_mma<<<dim3(16, 64), 128, gemm_smem>>>(a2, w2, nullptr, out, nullptr, 2048);
}

// round 16
// speedup vs baseline: 1.0350x; 1.0350x over previous
#include <cuda_runtime.h>
#include <cuda_fp16.h>
#include <math.h>
#include <stdint.h>

// Problem constants (Gemma2 attention layer)
#define B_ 4
#define S_ 2048
#define H_ 2048
#define NH_ 8
#define NKV_ 4
#define HD_ 256
#define WIN_ 1024
#define SCALE_ 0.0625f   // 256^-0.5

#define GK_   2048       // inner K of every GEMM
#define KC    64         // K-chunk per pipeline stage
#define NC    32         // GK_ / KC
#define NSTAGE 3
#define STGB  16384      // bytes per operand stage (128 rows x 128B, packed)

// ---------------------------------------------------------------------------
// Scratch (device globals — no allocation allowed)
// ---------------------------------------------------------------------------
__device__ float g_qkv[(size_t)B_ * S_ * 4096];               // Q(2048)|K(1024)|V(1024)
__device__ float g_bias4[4096];
__device__ __half g_a2[(size_t)B_ * S_ * GK_];                // 32 MB (single fp16)
__device__ __half g_w2[(size_t)4096 * GK_];                   // 16 MB (single fp16)
__device__ float2 g_rope[(size_t)B_ * S_ * 128];              // cos/sin table
// attention operands
__device__ __half g_q2[(size_t)B_ * NH_ * S_ * 256];          // [b][h][s][q(256)]
__device__ __half g_k2[(size_t)B_ * NKV_ * S_ * 256];         // [b][kvh][s][k(256)]
__device__ __half g_vt[(size_t)B_ * NKV_ * 256 * S_];         // [b][kvh][d(256)][s]

// ---------------------------------------------------------------------------
// Helpers
// ---------------------------------------------------------------------------
__device__ __forceinline__ uint32_t smem_u32(const void* p) {
    uint32_t a;
    asm("{ .reg .u64 t; cvta.to.shared.u64 t, %1; cvt.u32.u64 %0, t; }" : "=r"(a) : "l"(p));
    return a;
}
__device__ __forceinline__ void cp16(uint32_t dst, const void* src) {
    asm volatile("cp.async.cg.shared.global [%0], [%1], 16;" :: "r"(dst), "l"(src));
}
#define CP_COMMIT() asm volatile("cp.async.commit_group;" ::: "memory")
#define CP_WAIT1()  asm volatile("cp.async.wait_group 1;" ::: "memory")
#define CP_WAIT2()  asm volatile("cp.async.wait_group 2;" ::: "memory")

__device__ __forceinline__ void mma16816(float* c, const uint32_t* a, const uint32_t* b) {
    asm volatile(
        "mma.sync.aligned.m16n8k16.row.col.f32.f16.f16.f32 "
        "{%0,%1,%2,%3}, {%4,%5,%6,%7}, {%8,%9}, {%0,%1,%2,%3};"
        : "+f"(c[0]), "+f"(c[1]), "+f"(c[2]), "+f"(c[3])
        : "r"(a[0]), "r"(a[1]), "r"(a[2]), "r"(a[3]), "r"(b[0]), "r"(b[1]));
}
#define LDSM4(r, a)                                                             \
    asm volatile("ldmatrix.sync.aligned.m8n8.x4.shared.b16 {%0,%1,%2,%3}, [%4];" \
        : "=r"((r)[0]), "=r"((r)[1]), "=r"((r)[2]), "=r"((r)[3]) : "r"(a))

// ---------------------------------------------------------------------------
// RoPE table + bias concat fused (bias blocks appended at grid tail)
// ---------------------------------------------------------------------------
__global__ __launch_bounds__(256) void rope_bias(
    const int* __restrict__ positions, float2* __restrict__ T,
    const float* __restrict__ bq, const float* __restrict__ bk,
    const float* __restrict__ bv, float* __restrict__ bdst)
{
    const int nrope = (B_ * S_ * 128) / 256;      // 4096 blocks of rope work
    if (blockIdx.x < nrope) {
        int idx = blockIdx.x * 256 + threadIdx.x;
        int d = idx & 127;
        int bs = idx >> 7;
        int pos = positions[bs];
        float inv_freq = exp2f(-(float)d * 0.103810253f);
        float fr = (float)pos * inv_freq;
        float sn, cs;
        sincosf(fr, &sn, &cs);
        T[idx] = make_float2(cs, sn);
    } else {
        int i = (blockIdx.x - nrope) * 256 + threadIdx.x;   // 0..4095
        float v;
        if (i < 2048) v = bq[i];
        else if (i < 3072) v = bk[i - 2048];
        else v = bv[i - 3072];
        bdst[i] = v;
    }
}

// ---------------------------------------------------------------------------
// Conversions for GEMM
// ---------------------------------------------------------------------------
__global__ __launch_bounds__(256) void convA2(const float* __restrict__ A,
                                              __half* __restrict__ A2)
{
    int idx = blockIdx.x * 256 + threadIdx.x;
    int m = idx >> 9;
    int j = (idx & 511) * 4;
    float4 v = *(const float4*)(A + (size_t)m * GK_ + j);
    __half h[4] = {__float2half_rn(v.x), __float2half_rn(v.y),
                   __float2half_rn(v.z), __float2half_rn(v.w)};
    *(uint2*)&A2[(size_t)m * GK_ + j] = *(uint2*)h;
}

__global__ __launch_bounds__(256) void convW2(const float* __restrict__ W,
                                              __half* __restrict__ W2, int N)
{
    __shared__ float t[32][33];
    int n0 = blockIdx.x * 32, k0 = blockIdx.y * 32;
    int tx = threadIdx.x & 31, ty = threadIdx.x >> 5;
#pragma unroll
    for (int i = 0; i < 32; i += 8)
        t[ty + i][tx] = W[(size_t)(k0 + ty + i) * N + n0 + tx];
    __syncthreads();
#pragma unroll
    for (int i = 0; i < 32; i += 8) {
        int n = n0 + ty + i, k = k0 + tx;
        W2[(size_t)n * GK_ + k] = __float2half_rn(t[tx][ty + i]);
    }
}

// ---------------------------------------------------------------------------
// mma.sync fp16 GEMM: C[8192,Nn] = A2[8192,2048] @ W2[Nn,2048]^T + bias
// 128 threads (4 warps, 2m x 2n), warp tile 64x64; packed swizzled stages,
// 2 CTAs/SM.
// ---------------------------------------------------------------------------
__global__ __launch_bounds__(128, 2) void gemm_mma(
    const __half* __restrict__ A2, const __half* __restrict__ B2,
    const float* __restrict__ bias, float* __restrict__ C, int Nn)
{
    extern __shared__ __align__(16) char smraw[];
    const uint32_t sAu = smem_u32(smraw);                  // 3 stages x 16KB
    const uint32_t sBu = sAu + NSTAGE * STGB;              // 3 stages x 16KB
    float* sbias = (float*)(smraw + 2 * NSTAGE * STGB);    // [128]

    const int tid = threadIdx.x;
    const int m0 = blockIdx.y * 128;
    const int n0 = blockIdx.x * 128;

    sbias[tid] = bias ? bias[n0 + tid] : 0.f;

    const int seg = tid & 7;
    const int r0  = tid >> 3;                              // 0..15
    const uint32_t stOff = (uint32_t)(r0 * 128) + (uint32_t)(((seg ^ (r0 & 7)) & 7) << 4);
    const __half* Ag = A2 + (size_t)m0 * GK_ + seg * 8;
    const __half* Bg = B2 + (size_t)n0 * GK_ + seg * 8;

#define LOAD_STAGE(chunk, st) do {                                              \
    int _k0 = (chunk) * KC;                                                     \
    uint32_t _da = sAu + (uint32_t)(st) * STGB + stOff;                         \
    uint32_t _db = sBu + (uint32_t)(st) * STGB + stOff;                         \
    _Pragma("unroll")                                                           \
    for (int _rr = 0; _rr < 8; _rr++) {                                         \
        int _row = r0 + _rr * 16;                                               \
        cp16(_da + _rr * 2048u, Ag + (size_t)_row * GK_ + _k0);                 \
        cp16(_db + _rr * 2048u, Bg + (size_t)_row * GK_ + _k0);                 \
    }                                                                           \
} while (0)

    const int wid = tid >> 5, lane = tid & 31;
    const int wm = (wid >> 1) * 64;
    const int wn = (wid & 1) * 64;
    const int g = lane >> 2, t = lane & 3;

    const int hiA = lane >> 4;
    const int maskA = lane & 7;
    const uint32_t aByte = (uint32_t)((wm + (lane & 15)) * 128);
    const int hiB = (lane >> 3) & 1;
    const int maskB = lane & 7;
    const uint32_t bByte = (uint32_t)((wn + ((lane >> 4) << 3) + (lane & 7)) * 128);

    float acc[4][8][4];
#pragma unroll
    for (int mi = 0; mi < 4; mi++)
#pragma unroll
        for (int ni = 0; ni < 8; ni++)
#pragma unroll
            for (int e = 0; e < 4; e++) acc[mi][ni][e] = 0.f;

    LOAD_STAGE(0, 0); CP_COMMIT();
    LOAD_STAGE(1, 1); CP_COMMIT();

    for (int c = 0; c < NC; c++) {
        CP_WAIT1();
        __syncthreads();

        int lc = c + 2;
        int st_ld = lc - (lc / 3) * 3;
        if (lc < NC) LOAD_STAGE(lc, st_ld);
        CP_COMMIT();

        int st = c - (c / 3) * 3;
        const uint32_t aS = sAu + st * STGB + aByte;
        const uint32_t bS = sBu + st * STGB + bByte;

#pragma unroll
        for (int ks = 0; ks < 4; ks++) {
            const uint32_t offA = (uint32_t)(((2 * ks + hiA) ^ maskA) << 4);
            const uint32_t offB = (uint32_t)(((2 * ks + hiB) ^ maskB) << 4);
            uint32_t af[4][4], bq4[4][4];
#pragma unroll
            for (int mi = 0; mi < 4; mi++) LDSM4(af[mi], aS + mi * 2048u + offA);
#pragma unroll
            for (int p = 0; p < 4; p++) LDSM4(bq4[p], bS + p * 2048u + offB);
#pragma unroll
            for (int mi = 0; mi < 4; mi++)
#pragma unroll
                for (int ni = 0; ni < 8; ni++)
                    mma16816(acc[mi][ni], af[mi], &bq4[ni >> 1][(ni & 1) * 2]);
        }
    }

    __syncthreads();
#pragma unroll
    for (int mi = 0; mi < 4; mi++) {
        int row = m0 + wm + mi * 16 + g;
#pragma unroll
        for (int ni = 0; ni < 8; ni++) {
            int lcol = wn + ni * 8 + 2 * t;
            float b0 = sbias[lcol], b1 = sbias[lcol + 1];
            float2 v0 = {acc[mi][ni][0] + b0, acc[mi][ni][1] + b1};
            float2 v1 = {acc[mi][ni][2] + b0, acc[mi][ni][3] + b1};
            *(float2*)(C + (size_t)row * Nn + n0 + lcol) = v0;
            *(float2*)(C + (size_t)(row + 8) * Nn + n0 + lcol) = v1;
        }
    }
#undef LOAD_STAGE
}

// ---------------------------------------------------------------------------
// Fused RoPE (table) + scale + fp16 conversion for Q and K.
// ---------------------------------------------------------------------------
__global__ __launch_bounds__(256) void conv_qk(
    const float* __restrict__ qkv, const float2* __restrict__ T,
    __half* __restrict__ Q2, __half* __restrict__ K2)
{
    int idx = blockIdx.x * 256 + threadIdx.x;   // 4*2048*12*32
    int dg = idx & 31;
    int r = idx >> 5;
    int head = r % 12;
    int bs = r / 12;
    int b = bs >> 11, s = bs & 2047;
    int d0 = dg * 4;

    const bool isq = head < NH_;
    const float* src = qkv + (size_t)bs * 4096 + head * HD_;
    const float sc = isq ? SCALE_ : 1.0f;

    float4 x1 = *(const float4*)(src + d0);
    float4 x2 = *(const float4*)(src + d0 + 128);
    float a1[4] = {x1.x, x1.y, x1.z, x1.w};
    float a2[4] = {x2.x, x2.y, x2.z, x2.w};
    __half h1[4], h2[4];
#pragma unroll
    for (int e = 0; e < 4; e++) {
        float2 cssn = T[(size_t)bs * 128 + d0 + e];
        float y1 = (a1[e] * cssn.x - a2[e] * cssn.y) * sc;
        float y2 = (a2[e] * cssn.x + a1[e] * cssn.y) * sc;
        h1[e] = __float2half_rn(y1);
        h2[e] = __float2half_rn(y2);
    }
    __half* dst = isq ? (Q2 + ((size_t)(b * NH_ + head) * S_ + s) * 256)
                      : (K2 + ((size_t)(b * NKV_ + head - NH_) * S_ + s) * 256);
    *(uint2*)(dst + d0)       = *(uint2*)h1;
    *(uint2*)(dst + 128 + d0) = *(uint2*)h2;
}

// ---------------------------------------------------------------------------
// V transpose + single fp16: qkv cols [3072,4096) -> g_vt [b][kvh][256][S]
// ---------------------------------------------------------------------------
__global__ __launch_bounds__(256) void conv_v(const float* __restrict__ qkv,
                                              __half* __restrict__ Vt)
{
    __shared__ float tile[32][33];
    int s0 = blockIdx.x * 32, d0 = blockIdx.y * 32;
    int b = blockIdx.z >> 2, kvh = blockIdx.z & 3;
    int tx = threadIdx.x & 31, ty = threadIdx.x >> 5;
#pragma unroll
    for (int i = 0; i < 32; i += 8)
        tile[ty + i][tx] = qkv[(size_t)(b * S_ + s0 + ty + i) * 4096 + 3072 + kvh * HD_ + d0 + tx];
    __syncthreads();
    size_t base = (size_t)(b * NKV_ + kvh) * 256;
#pragma unroll
    for (int i = 0; i < 32; i += 8) {
        int d = d0 + ty + i;
        Vt[(base + d) * S_ + s0 + tx] = __float2half_rn(tile[tx][ty + i]);
    }
}

// ---------------------------------------------------------------------------
// Tensor-core sliding-window flash attention (fp16).
// q-tile 128 (8 warps, 256 threads, 1 CTA/SM), kv-tile 64; double-buffered
// K+V; Q fragments hoisted; PV single-pass.
// ---------------------------------------------------------------------------
#define QROWB 512    // bytes per Q/K smem row (256 halfs, packed)
#define VLD 72       // fp16 elems per V smem row (64 + 8 pad), 144B
#define KSTG 32768   // bytes per K stage (64 x 512)
#define VSTG 36864   // bytes per V stage (256 x 144)

__global__ __launch_bounds__(256, 1) void attn_mma(
    const __half* __restrict__ Q2, const __half* __restrict__ K2,
    const __half* __restrict__ Vt, __half* __restrict__ A2out)
{
    extern __shared__ __align__(16) __half smb[];
    const uint32_t QsA = smem_u32(smb);                  // 128 x 512B = 64KB
    const uint32_t KsA = QsA + 128 * QROWB;              // 2 x 32KB
    const uint32_t VsA = KsA + 2 * KSTG;                 // 2 x 36KB  -> total 200KB

    const int tid = threadIdx.x;
    const int w = tid >> 5, lane = tid & 31;
    const int g = lane >> 2, t = lane & 3;
    const int q0 = blockIdx.x * 128;
    const int h = blockIdx.y;
    const int b = blockIdx.z;
    const int kvh = h >> 1;

    const __half* Qg = Q2 + ((size_t)(b * NH_ + h) * S_ + q0) * 256;
    const __half* Kg = K2 + (size_t)(b * NKV_ + kvh) * S_ * 256;
    const __half* Vg = Vt + (size_t)(b * NKV_ + kvh) * 256 * S_;

    const int hiQ = lane >> 4;
    const int maskQ = lane & 7;
    const uint32_t qByte = QsA + (uint32_t)((w * 16 + (lane & 15)) * QROWB);
    const int hiK = (lane >> 3) & 1;
    const int maskK = lane & 7;
    const uint32_t kBase = KsA + (uint32_t)((((lane >> 4) << 3) + (lane & 7)) * QROWB);
    const uint32_t vBase = VsA + (uint32_t)((((lane >> 4) << 3) + (lane & 7)) * VLD * 2 +
                                            ((lane >> 3) & 1) * 16);

    // ---- load Q tile (group 0): 128 rows x 256 elems
#pragma unroll
    for (int it = 0; it < 16; it++) {
        int idx = tid + it * 256;
        int r = idx >> 5, seg = idx & 31;
        uint32_t d = QsA + (uint32_t)(r * QROWB) + (uint32_t)((seg ^ (r & 7)) << 4);
        cp16(d, Qg + (size_t)r * 256 + seg * 8);
    }
    CP_COMMIT();

    int lo = q0 - (WIN_ - 1); if (lo < 0) lo = 0;
    const int kt0 = (lo >> 6) << 6;
    const int ntiles = ((q0 + 64) - kt0) / 64 + 1;

#define LOAD_KV(kt, st) do {                                                    \
    _Pragma("unroll")                                                           \
    for (int _it = 0; _it < 8; _it++) {                                         \
        int _i = tid + _it * 256;                                               \
        int _r = _i >> 5, _sg = _i & 31;                                        \
        uint32_t _d = KsA + (uint32_t)(st) * KSTG + (uint32_t)(_r * QROWB) +     \
                      (uint32_t)((_sg ^ (_r & 7)) << 4);                         \
        cp16(_d, Kg + ((size_t)((kt) + _r)) * 256 + _sg * 8);                   \
    }                                                                           \
    _Pragma("unroll")                                                           \
    for (int _it = 0; _it < 8; _it++) {                                         \
        int _i = tid + _it * 256;                                               \
        int _r = _i >> 3, _sg = _i & 7;                                         \
        cp16(VsA + (uint32_t)(st) * VSTG + (uint32_t)(_r * VLD + _sg * 8) * 2,  \
             Vg + (size_t)_r * S_ + (kt) + _sg * 8);                            \
    }                                                                           \
} while (0)

    LOAD_KV(kt0, 0); CP_COMMIT();                 // group 1
    if (ntiles > 1) LOAD_KV(kt0 + 64, 1);
    CP_COMMIT();                                   // group 2 (possibly empty)

    // ---- hoist Q fragments: wait for group 0 only
    CP_WAIT2();
    __syncthreads();
    uint32_t qf[16][4];
#pragma unroll
    for (int ks = 0; ks < 16; ks++) {
        const uint32_t offQ = (uint32_t)(((2 * ks + hiQ) ^ maskQ) << 4);
        LDSM4(qf[ks], qByte + offQ);
    }

    float o[32][4];
#pragma unroll
    for (int nt = 0; nt < 32; nt++)
#pragma unroll
        for (int e = 0; e < 4; e++) o[nt][e] = 0.f;
    float rmax0 = -1e20f, rmax1 = -1e20f, rsum0 = 0.f, rsum1 = 0.f;

    const int rmin = q0 + w * 16;
    const int rmax_w = rmin + 15;
    const int row0 = rmin + g;
    const int row1 = row0 + 8;
    const int tcol = 2 * t;

    for (int j = 0; j < ntiles; j++) {
        const int kt = kt0 + 64 * j;
        const int st = j & 1;
        const bool skipT = (kt > rmax_w) || (kt + 63 < rmin - (WIN_ - 1));
        const bool edge = !((kt + 63 <= rmin) && (kt >= rmax_w - (WIN_ - 1)));

        CP_WAIT1();            // KV_j resident (pending: KV_{j+1})
        __syncthreads();

        if (!skipT) {
            const uint32_t kByte = kBase + st * KSTG;
            const uint32_t vB = vBase + st * VSTG;
            float s[8][4];
#pragma unroll
            for (int nt = 0; nt < 8; nt++)
#pragma unroll
                for (int e = 0; e < 4; e++) s[nt][e] = 0.f;
#pragma unroll 2
            for (int ks = 0; ks < 16; ks++) {
                const uint32_t offK = (uint32_t)(((2 * ks + hiK) ^ maskK) << 4);
                uint32_t bb[4][4];
#pragma unroll
                for (int r16 = 0; r16 < 4; r16++)
                    LDSM4(bb[r16], kByte + r16 * (16 * QROWB) + offK);
#pragma unroll
                for (int nt = 0; nt < 8; nt++)
                    mma16816(s[nt], qf[ks], &bb[nt >> 1][(nt & 1) * 2]);
            }
            if (edge) {
#pragma unroll
                for (int nt = 0; nt < 8; nt++) {
                    int c0 = kt + nt * 8 + tcol, c1 = c0 + 1;
                    if (!(c0 <= row0 && c0 > row0 - WIN_)) s[nt][0] = -1e30f;
                    if (!(c1 <= row0 && c1 > row0 - WIN_)) s[nt][1] = -1e30f;
                    if (!(c0 <= row1 && c0 > row1 - WIN_)) s[nt][2] = -1e30f;
                    if (!(c1 <= row1 && c1 > row1 - WIN_)) s[nt][3] = -1e30f;
                }
            }
            float m0 = -1e30f, m1 = -1e30f;
#pragma unroll
            for (int nt = 0; nt < 8; nt++) {
                m0 = fmaxf(m0, fmaxf(s[nt][0], s[nt][1]));
                m1 = fmaxf(m1, fmaxf(s[nt][2], s[nt][3]));
            }
            m0 = fmaxf(m0, __shfl_xor_sync(0xffffffffu, m0, 1));
            m0 = fmaxf(m0, __shfl_xor_sync(0xffffffffu, m0, 2));
            m1 = fmaxf(m1, __shfl_xor_sync(0xffffffffu, m1, 1));
            m1 = fmaxf(m1, __shfl_xor_sync(0xffffffffu, m1, 2));
            float nm0 = fmaxf(rmax0, m0), nm1 = fmaxf(rmax1, m1);
            float al0 = __expf(rmax0 - nm0), al1 = __expf(rmax1 - nm1);
            float ls0 = 0.f, ls1 = 0.f;
#pragma unroll
            for (int nt = 0; nt < 8; nt++) {
                s[nt][0] = __expf(s[nt][0] - nm0);
                s[nt][1] = __expf(s[nt][1] - nm0);
                s[nt][2] = __expf(s[nt][2] - nm1);
                s[nt][3] = __expf(s[nt][3] - nm1);
                ls0 += s[nt][0] + s[nt][1];
                ls1 += s[nt][2] + s[nt][3];
            }
            ls0 += __shfl_xor_sync(0xffffffffu, ls0, 1);
            ls0 += __shfl_xor_sync(0xffffffffu, ls0, 2);
            ls1 += __shfl_xor_sync(0xffffffffu, ls1, 1);
            ls1 += __shfl_xor_sync(0xffffffffu, ls1, 2);
            rsum0 = rsum0 * al0 + ls0;
            rsum1 = rsum1 * al1 + ls1;
            rmax0 = nm0; rmax1 = nm1;
#pragma unroll
            for (int nt = 0; nt < 32; nt++) {
                o[nt][0] *= al0; o[nt][1] *= al0;
                o[nt][2] *= al1; o[nt][3] *= al1;
            }
            // PV: 4 key-chunks of 16; pack P fragments on the fly
#pragma unroll
            for (int kk = 0; kk < 4; kk++) {
                __half2 h01a = __floats2half2_rn(s[2 * kk][0], s[2 * kk][1]);
                __half2 h23a = __floats2half2_rn(s[2 * kk][2], s[2 * kk][3]);
                __half2 h01b = __floats2half2_rn(s[2 * kk + 1][0], s[2 * kk + 1][1]);
                __half2 h23b = __floats2half2_rn(s[2 * kk + 1][2], s[2 * kk + 1][3]);
                uint32_t Ah[4] = {*(uint32_t*)&h01a, *(uint32_t*)&h23a,
                                  *(uint32_t*)&h01b, *(uint32_t*)&h23b};
#pragma unroll
                for (int p = 0; p < 16; p++) {
                    uint32_t rv[4];
                    LDSM4(rv, vB + p * (16 * VLD * 2) + kk * 32);
                    mma16816(o[2 * p], Ah, &rv[0]);
                    mma16816(o[2 * p + 1], Ah, &rv[2]);
                }
            }
        }
        __syncthreads();       // all warps done with stage st
        int lj = j + 2;
        if (lj < ntiles) LOAD_KV(kt0 + 64 * lj, lj & 1);
        CP_COMMIT();           // always commit to keep group count uniform
    }

    // epilogue: normalize and write fp16 directly into A2
    float inv0 = 1.0f / rsum0, inv1 = 1.0f / rsum1;
    __half* d0p = A2out + (size_t)(b * S_ + row0) * GK_ + h * HD_;
    __half* d1p = A2out + (size_t)(b * S_ + row1) * GK_ + h * HD_;
#pragma unroll
    for (int nt = 0; nt < 32; nt++) {
        int d = nt * 8 + tcol;
        __half2 v0 = __floats2half2_rn(o[nt][0] * inv0, o[nt][1] * inv0);
        __half2 v1 = __floats2half2_rn(o[nt][2] * inv1, o[nt][3] * inv1);
        *(__half2*)(d0p + d) = v0;
        *(__half2*)(d1p + d) = v1;
    }
#undef LOAD_KV
}

// ---------------------------------------------------------------------------
// Launch
// ---------------------------------------------------------------------------
extern "C" void kernel_launch(void* const* d_in, const int* in_sizes, int n_in,
                              void* d_out, int out_size)
{
    const float* hidden    = (const float*)d_in[0];
    const int*   positions = (const int*)d_in[1];
    const float* Wq        = (const float*)d_in[2];
    const float* bq        = (const float*)d_in[3];
    const float* Wk        = (const float*)d_in[4];
    const float* bk        = (const float*)d_in[5];
    const float* Wv        = (const float*)d_in[6];
    const float* bv        = (const float*)d_in[7];
    const float* Wo        = (const float*)d_in[8];
    float* out = (float*)d_out;

    float *qkv, *b4;
    float2* rt;
    __half *a2, *w2, *q2, *k2, *vt;
    cudaGetSymbolAddress((void**)&qkv, g_qkv);
    cudaGetSymbolAddress((void**)&b4, g_bias4);
    cudaGetSymbolAddress((void**)&a2, g_a2);
    cudaGetSymbolAddress((void**)&w2, g_w2);
    cudaGetSymbolAddress((void**)&rt, g_rope);
    cudaGetSymbolAddress((void**)&q2, g_q2);
    cudaGetSymbolAddress((void**)&k2, g_k2);
    cudaGetSymbolAddress((void**)&vt, g_vt);

    const int M = B_ * S_;
    const size_t gemm_smem = (size_t)2 * NSTAGE * STGB + 512;   // 98,816 B
    cudaFuncSetAttribute(gemm_mma, cudaFuncAttributeMaxDynamicSharedMemorySize, (int)gemm_smem);

    // fused rope table + bias concat
    rope_bias<<<(B_ * S_ * 128) / 256 + 16, 256>>>(positions, rt, bq, bk, bv, b4);
    convA2<<<M * 512 / 256, 256>>>(hidden, a2);

    // merged Q|K|V projection (N=4096)
    convW2<<<dim3(2048 / 32, 64), 256>>>(Wq, w2, 2048);
    convW2<<<dim3(1024 / 32, 64), 256>>>(Wk, w2 + (size_t)2048 * GK_, 1024);
    convW2<<<dim3(1024 / 32, 64), 256>>>(Wv, w2 + (size_t)3072 * GK_, 1024);
    gemm_mma<<<dim3(32, 64), 128, gemm_smem>>>(a2, w2, b4, qkv, 4096);

    conv_qk<<<(B_ * S_ * 12 * 32) / 256, 256>>>(qkv, rt, q2, k2);
    conv_v<<<dim3(S_ / 32, HD_ / 32, B_ * NKV_), 256>>>(qkv, vt);

    // attention writes fp16 directly into A2
    {
        size_t smem = (size_t)(128 * QROWB + 2 * KSTG + 2 * VSTG);  // 204,800 B
        cudaFuncSetAttribute(attn_mma, cudaFuncAttributeMaxDynamicSharedMemorySize, (int)smem);
        attn_mma<<<dim3(S_ / 128, NH_, B_), 256, smem>>>(q2, k2, vt, a2);
    }

    // O projection
    convW2<<<dim3(2048 / 32, 64), 256>>>(Wo, w2, 2048);
    gemm_mma<<<dim3(16, 64), 128, gemm_smem>>>(a2, w2, nullptr, out, 2048);
}

// round 17
// speedup vs baseline: 1.0420x; 1.0068x over previous
#include <cuda_runtime.h>
#include <cuda_fp16.h>
#include <math.h>
#include <stdint.h>

// Problem constants (Gemma2 attention layer)
#define B_ 4
#define S_ 2048
#define H_ 2048
#define NH_ 8
#define NKV_ 4
#define HD_ 256
#define WIN_ 1024
#define SCALE_ 0.0625f   // 256^-0.5

#define GK_   2048       // inner K of every GEMM
#define KC    64         // K-chunk per pipeline stage
#define NC    32         // GK_ / KC
#define NSTAGE 3
#define STGB  16384      // bytes per operand stage (128 rows x 128B, packed)

// ---------------------------------------------------------------------------
// Scratch (device globals — no allocation allowed)
// ---------------------------------------------------------------------------
__device__ float g_qkv[(size_t)B_ * S_ * 4096];               // Q(2048)|K(1024)|V(1024)
__device__ float g_bias4[4096];
__device__ __half g_a2[(size_t)B_ * S_ * GK_];                // 32 MB (single fp16)
__device__ __half g_w2[(size_t)4096 * GK_];                   // 16 MB (single fp16)
__device__ float2 g_rope[(size_t)B_ * S_ * 128];              // cos/sin table
// attention operands
__device__ __half g_q2[(size_t)B_ * NH_ * S_ * 256];          // [b][h][s][q(256)]
__device__ __half g_k2[(size_t)B_ * NKV_ * S_ * 256];         // [b][kvh][s][k(256)]
__device__ __half g_vt[(size_t)B_ * NKV_ * 256 * S_];         // [b][kvh][d(256)][s]

// ---------------------------------------------------------------------------
// Helpers
// ---------------------------------------------------------------------------
__device__ __forceinline__ uint32_t smem_u32(const void* p) {
    uint32_t a;
    asm("{ .reg .u64 t; cvta.to.shared.u64 t, %1; cvt.u32.u64 %0, t; }" : "=r"(a) : "l"(p));
    return a;
}
__device__ __forceinline__ void cp16(uint32_t dst, const void* src) {
    asm volatile("cp.async.cg.shared.global [%0], [%1], 16;" :: "r"(dst), "l"(src));
}
#define CP_COMMIT() asm volatile("cp.async.commit_group;" ::: "memory")
#define CP_WAIT1()  asm volatile("cp.async.wait_group 1;" ::: "memory")
#define CP_WAIT2()  asm volatile("cp.async.wait_group 2;" ::: "memory")

__device__ __forceinline__ void mma16816(float* c, const uint32_t* a, const uint32_t* b) {
    asm volatile(
        "mma.sync.aligned.m16n8k16.row.col.f32.f16.f16.f32 "
        "{%0,%1,%2,%3}, {%4,%5,%6,%7}, {%8,%9}, {%0,%1,%2,%3};"
        : "+f"(c[0]), "+f"(c[1]), "+f"(c[2]), "+f"(c[3])
        : "r"(a[0]), "r"(a[1]), "r"(a[2]), "r"(a[3]), "r"(b[0]), "r"(b[1]));
}
#define LDSM4(r, a)                                                             \
    asm volatile("ldmatrix.sync.aligned.m8n8.x4.shared.b16 {%0,%1,%2,%3}, [%4];" \
        : "=r"((r)[0]), "=r"((r)[1]), "=r"((r)[2]), "=r"((r)[3]) : "r"(a))

// ---------------------------------------------------------------------------
// RoPE table + bias concat fused (bias blocks appended at grid tail)
// ---------------------------------------------------------------------------
__global__ __launch_bounds__(256) void rope_bias(
    const int* __restrict__ positions, float2* __restrict__ T,
    const float* __restrict__ bq, const float* __restrict__ bk,
    const float* __restrict__ bv, float* __restrict__ bdst)
{
    const int nrope = (B_ * S_ * 128) / 256;      // 4096 blocks of rope work
    if (blockIdx.x < nrope) {
        int idx = blockIdx.x * 256 + threadIdx.x;
        int d = idx & 127;
        int bs = idx >> 7;
        int pos = positions[bs];
        float inv_freq = exp2f(-(float)d * 0.103810253f);
        float fr = (float)pos * inv_freq;
        float sn, cs;
        sincosf(fr, &sn, &cs);
        T[idx] = make_float2(cs, sn);
    } else {
        int i = (blockIdx.x - nrope) * 256 + threadIdx.x;   // 0..4095
        float v;
        if (i < 2048) v = bq[i];
        else if (i < 3072) v = bk[i - 2048];
        else v = bv[i - 3072];
        bdst[i] = v;
    }
}

// ---------------------------------------------------------------------------
// Conversions for GEMM
// ---------------------------------------------------------------------------
__global__ __launch_bounds__(256) void convA2(const float* __restrict__ A,
                                              __half* __restrict__ A2)
{
    int idx = blockIdx.x * 256 + threadIdx.x;
    int m = idx >> 9;
    int j = (idx & 511) * 4;
    float4 v = *(const float4*)(A + (size_t)m * GK_ + j);
    __half h[4] = {__float2half_rn(v.x), __float2half_rn(v.y),
                   __float2half_rn(v.z), __float2half_rn(v.w)};
    *(uint2*)&A2[(size_t)m * GK_ + j] = *(uint2*)h;
}

// single convW2 (used for Wo)
__global__ __launch_bounds__(256) void convW2(const float* __restrict__ W,
                                              __half* __restrict__ W2, int N)
{
    __shared__ float t[32][33];
    int n0 = blockIdx.x * 32, k0 = blockIdx.y * 32;
    int tx = threadIdx.x & 31, ty = threadIdx.x >> 5;
#pragma unroll
    for (int i = 0; i < 32; i += 8)
        t[ty + i][tx] = W[(size_t)(k0 + ty + i) * N + n0 + tx];
    __syncthreads();
#pragma unroll
    for (int i = 0; i < 32; i += 8) {
        int n = n0 + ty + i, k = k0 + tx;
        W2[(size_t)n * GK_ + k] = __float2half_rn(t[tx][ty + i]);
    }
}

// merged Wq|Wk|Wv conversion: bx<64 -> Wq(2048), bx<96 -> Wk(1024), else Wv(1024)
__global__ __launch_bounds__(256) void convW3(const float* __restrict__ Wq,
                                              const float* __restrict__ Wk,
                                              const float* __restrict__ Wv,
                                              __half* __restrict__ W2)
{
    __shared__ float t[32][33];
    const int bx = blockIdx.x;
    const float* W;
    int N, n0, rowoff;
    if (bx < 64)      { W = Wq; N = 2048; n0 = bx * 32;        rowoff = 0; }
    else if (bx < 96) { W = Wk; N = 1024; n0 = (bx - 64) * 32; rowoff = 2048; }
    else              { W = Wv; N = 1024; n0 = (bx - 96) * 32; rowoff = 3072; }
    int k0 = blockIdx.y * 32;
    int tx = threadIdx.x & 31, ty = threadIdx.x >> 5;
#pragma unroll
    for (int i = 0; i < 32; i += 8)
        t[ty + i][tx] = W[(size_t)(k0 + ty + i) * N + n0 + tx];
    __syncthreads();
#pragma unroll
    for (int i = 0; i < 32; i += 8) {
        int n = n0 + ty + i, k = k0 + tx;
        W2[(size_t)(rowoff + n) * GK_ + k] = __float2half_rn(t[tx][ty + i]);
    }
}

// ---------------------------------------------------------------------------
// mma.sync fp16 GEMM: C[8192,Nn] = A2[8192,2048] @ W2[Nn,2048]^T + bias
// 128 threads (4 warps, 2m x 2n), warp tile 64x64; packed swizzled stages,
// 2 CTAs/SM.
// ---------------------------------------------------------------------------
__global__ __launch_bounds__(128, 2) void gemm_mma(
    const __half* __restrict__ A2, const __half* __restrict__ B2,
    const float* __restrict__ bias, float* __restrict__ C, int Nn)
{
    extern __shared__ __align__(16) char smraw[];
    const uint32_t sAu = smem_u32(smraw);                  // 3 stages x 16KB
    const uint32_t sBu = sAu + NSTAGE * STGB;              // 3 stages x 16KB
    float* sbias = (float*)(smraw + 2 * NSTAGE * STGB);    // [128]

    const int tid = threadIdx.x;
    const int m0 = blockIdx.y * 128;
    const int n0 = blockIdx.x * 128;

    sbias[tid] = bias ? bias[n0 + tid] : 0.f;

    const int seg = tid & 7;
    const int r0  = tid >> 3;                              // 0..15
    const uint32_t stOff = (uint32_t)(r0 * 128) + (uint32_t)(((seg ^ (r0 & 7)) & 7) << 4);
    const __half* Ag = A2 + (size_t)m0 * GK_ + seg * 8;
    const __half* Bg = B2 + (size_t)n0 * GK_ + seg * 8;

#define LOAD_STAGE(chunk, st) do {                                              \
    int _k0 = (chunk) * KC;                                                     \
    uint32_t _da = sAu + (uint32_t)(st) * STGB + stOff;                         \
    uint32_t _db = sBu + (uint32_t)(st) * STGB + stOff;                         \
    _Pragma("unroll")                                                           \
    for (int _rr = 0; _rr < 8; _rr++) {                                         \
        int _row = r0 + _rr * 16;                                               \
        cp16(_da + _rr * 2048u, Ag + (size_t)_row * GK_ + _k0);                 \
        cp16(_db + _rr * 2048u, Bg + (size_t)_row * GK_ + _k0);                 \
    }                                                                           \
} while (0)

    const int wid = tid >> 5, lane = tid & 31;
    const int wm = (wid >> 1) * 64;
    const int wn = (wid & 1) * 64;
    const int g = lane >> 2, t = lane & 3;

    const int hiA = lane >> 4;
    const int maskA = lane & 7;
    const uint32_t aByte = (uint32_t)((wm + (lane & 15)) * 128);
    const int hiB = (lane >> 3) & 1;
    const int maskB = lane & 7;
    const uint32_t bByte = (uint32_t)((wn + ((lane >> 4) << 3) + (lane & 7)) * 128);

    float acc[4][8][4];
#pragma unroll
    for (int mi = 0; mi < 4; mi++)
#pragma unroll
        for (int ni = 0; ni < 8; ni++)
#pragma unroll
            for (int e = 0; e < 4; e++) acc[mi][ni][e] = 0.f;

    LOAD_STAGE(0, 0); CP_COMMIT();
    LOAD_STAGE(1, 1); CP_COMMIT();

    for (int c = 0; c < NC; c++) {
        CP_WAIT1();
        __syncthreads();

        int lc = c + 2;
        int st_ld = lc - (lc / 3) * 3;
        if (lc < NC) LOAD_STAGE(lc, st_ld);
        CP_COMMIT();

        int st = c - (c / 3) * 3;
        const uint32_t aS = sAu + st * STGB + aByte;
        const uint32_t bS = sBu + st * STGB + bByte;

#pragma unroll
        for (int ks = 0; ks < 4; ks++) {
            const uint32_t offA = (uint32_t)(((2 * ks + hiA) ^ maskA) << 4);
            const uint32_t offB = (uint32_t)(((2 * ks + hiB) ^ maskB) << 4);
            uint32_t af[4][4], bq4[4][4];
#pragma unroll
            for (int mi = 0; mi < 4; mi++) LDSM4(af[mi], aS + mi * 2048u + offA);
#pragma unroll
            for (int p = 0; p < 4; p++) LDSM4(bq4[p], bS + p * 2048u + offB);
#pragma unroll
            for (int mi = 0; mi < 4; mi++)
#pragma unroll
                for (int ni = 0; ni < 8; ni++)
                    mma16816(acc[mi][ni], af[mi], &bq4[ni >> 1][(ni & 1) * 2]);
        }
    }

    __syncthreads();
#pragma unroll
    for (int mi = 0; mi < 4; mi++) {
        int row = m0 + wm + mi * 16 + g;
#pragma unroll
        for (int ni = 0; ni < 8; ni++) {
            int lcol = wn + ni * 8 + 2 * t;
            float b0 = sbias[lcol], b1 = sbias[lcol + 1];
            float2 v0 = {acc[mi][ni][0] + b0, acc[mi][ni][1] + b1};
            float2 v1 = {acc[mi][ni][2] + b0, acc[mi][ni][3] + b1};
            *(float2*)(C + (size_t)row * Nn + n0 + lcol) = v0;
            *(float2*)(C + (size_t)(row + 8) * Nn + n0 + lcol) = v1;
        }
    }
#undef LOAD_STAGE
}

// ---------------------------------------------------------------------------
// Merged conversion: blocks [0, 12288) = RoPE Q/K -> fp16; blocks
// [12288, 20480) = V transpose -> fp16. Branch is uniform per block.
// ---------------------------------------------------------------------------
#define NQKBLK 12288   // (B_*S_*12*32)/256

__global__ __launch_bounds__(256) void conv_qkv(
    const float* __restrict__ qkv, const float2* __restrict__ T,
    __half* __restrict__ Q2, __half* __restrict__ K2, __half* __restrict__ Vt)
{
    __shared__ float tile[32][33];
    if (blockIdx.x < NQKBLK) {
        int idx = blockIdx.x * 256 + threadIdx.x;   // 4*2048*12*32
        int dg = idx & 31;
        int r = idx >> 5;
        int head = r % 12;
        int bs = r / 12;
        int b = bs >> 11, s = bs & 2047;
        int d0 = dg * 4;

        const bool isq = head < NH_;
        const float* src = qkv + (size_t)bs * 4096 + head * HD_;
        const float sc = isq ? SCALE_ : 1.0f;

        float4 x1 = *(const float4*)(src + d0);
        float4 x2 = *(const float4*)(src + d0 + 128);
        float a1[4] = {x1.x, x1.y, x1.z, x1.w};
        float a2[4] = {x2.x, x2.y, x2.z, x2.w};
        __half h1[4], h2[4];
#pragma unroll
        for (int e = 0; e < 4; e++) {
            float2 cssn = T[(size_t)bs * 128 + d0 + e];
            float y1 = (a1[e] * cssn.x - a2[e] * cssn.y) * sc;
            float y2 = (a2[e] * cssn.x + a1[e] * cssn.y) * sc;
            h1[e] = __float2half_rn(y1);
            h2[e] = __float2half_rn(y2);
        }
        __half* dst = isq ? (Q2 + ((size_t)(b * NH_ + head) * S_ + s) * 256)
                          : (K2 + ((size_t)(b * NKV_ + head - NH_) * S_ + s) * 256);
        *(uint2*)(dst + d0)       = *(uint2*)h1;
        *(uint2*)(dst + 128 + d0) = *(uint2*)h2;
    } else {
        int z = blockIdx.x - NQKBLK;                 // 0..8191
        int s0 = (z & 63) * 32;
        int d0 = ((z >> 6) & 7) * 32;
        int bz = z >> 9;                             // 0..15
        int b = bz >> 2, kvh = bz & 3;
        int tx = threadIdx.x & 31, ty = threadIdx.x >> 5;
#pragma unroll
        for (int i = 0; i < 32; i += 8)
            tile[ty + i][tx] =
                qkv[(size_t)(b * S_ + s0 + ty + i) * 4096 + 3072 + kvh * HD_ + d0 + tx];
        __syncthreads();
        size_t base = (size_t)(b * NKV_ + kvh) * 256;
#pragma unroll
        for (int i = 0; i < 32; i += 8) {
            int d = d0 + ty + i;
            Vt[(base + d) * S_ + s0 + tx] = __float2half_rn(tile[tx][ty + i]);
        }
    }
}

// ---------------------------------------------------------------------------
// Tensor-core sliding-window flash attention (fp16).
// q-tile 128 (8 warps, 256 threads, 1 CTA/SM), kv-tile 64; double-buffered
// K+V; Q fragments hoisted; PV single-pass.
// ---------------------------------------------------------------------------
#define QROWB 512    // bytes per Q/K smem row (256 halfs, packed)
#define VLD 72       // fp16 elems per V smem row (64 + 8 pad), 144B
#define KSTG 32768   // bytes per K stage (64 x 512)
#define VSTG 36864   // bytes per V stage (256 x 144)

__global__ __launch_bounds__(256, 1) void attn_mma(
    const __half* __restrict__ Q2, const __half* __restrict__ K2,
    const __half* __restrict__ Vt, __half* __restrict__ A2out)
{
    extern __shared__ __align__(16) __half smb[];
    const uint32_t QsA = smem_u32(smb);                  // 128 x 512B = 64KB
    const uint32_t KsA = QsA + 128 * QROWB;              // 2 x 32KB
    const uint32_t VsA = KsA + 2 * KSTG;                 // 2 x 36KB  -> total 200KB

    const int tid = threadIdx.x;
    const int w = tid >> 5, lane = tid & 31;
    const int g = lane >> 2, t = lane & 3;
    const int q0 = blockIdx.x * 128;
    const int h = blockIdx.y;
    const int b = blockIdx.z;
    const int kvh = h >> 1;

    const __half* Qg = Q2 + ((size_t)(b * NH_ + h) * S_ + q0) * 256;
    const __half* Kg = K2 + (size_t)(b * NKV_ + kvh) * S_ * 256;
    const __half* Vg = Vt + (size_t)(b * NKV_ + kvh) * 256 * S_;

    const int hiQ = lane >> 4;
    const int maskQ = lane & 7;
    const uint32_t qByte = QsA + (uint32_t)((w * 16 + (lane & 15)) * QROWB);
    const int hiK = (lane >> 3) & 1;
    const int maskK = lane & 7;
    const uint32_t kBase = KsA + (uint32_t)((((lane >> 4) << 3) + (lane & 7)) * QROWB);
    const uint32_t vBase = VsA + (uint32_t)((((lane >> 4) << 3) + (lane & 7)) * VLD * 2 +
                                            ((lane >> 3) & 1) * 16);

    // ---- load Q tile (group 0): 128 rows x 256 elems
#pragma unroll
    for (int it = 0; it < 16; it++) {
        int idx = tid + it * 256;
        int r = idx >> 5, seg = idx & 31;
        uint32_t d = QsA + (uint32_t)(r * QROWB) + (uint32_t)((seg ^ (r & 7)) << 4);
        cp16(d, Qg + (size_t)r * 256 + seg * 8);
    }
    CP_COMMIT();

    int lo = q0 - (WIN_ - 1); if (lo < 0) lo = 0;
    const int kt0 = (lo >> 6) << 6;
    const int ntiles = ((q0 + 64) - kt0) / 64 + 1;

#define LOAD_KV(kt, st) do {                                                    \
    _Pragma("unroll")                                                           \
    for (int _it = 0; _it < 8; _it++) {                                         \
        int _i = tid + _it * 256;                                               \
        int _r = _i >> 5, _sg = _i & 31;                                        \
        uint32_t _d = KsA + (uint32_t)(st) * KSTG + (uint32_t)(_r * QROWB) +     \
                      (uint32_t)((_sg ^ (_r & 7)) << 4);                         \
        cp16(_d, Kg + ((size_t)((kt) + _r)) * 256 + _sg * 8);                   \
    }                                                                           \
    _Pragma("unroll")                                                           \
    for (int _it = 0; _it < 8; _it++) {                                         \
        int _i = tid + _it * 256;                                               \
        int _r = _i >> 3, _sg = _i & 7;                                         \
        cp16(VsA + (uint32_t)(st) * VSTG + (uint32_t)(_r * VLD + _sg * 8) * 2,  \
             Vg + (size_t)_r * S_ + (kt) + _sg * 8);                            \
    }                                                                           \
} while (0)

    LOAD_KV(kt0, 0); CP_COMMIT();                 // group 1
    if (ntiles > 1) LOAD_KV(kt0 + 64, 1);
    CP_COMMIT();                                   // group 2 (possibly empty)

    // ---- hoist Q fragments: wait for group 0 only
    CP_WAIT2();
    __syncthreads();
    uint32_t qf[16][4];
#pragma unroll
    for (int ks = 0; ks < 16; ks++) {
        const uint32_t offQ = (uint32_t)(((2 * ks + hiQ) ^ maskQ) << 4);
        LDSM4(qf[ks], qByte + offQ);
    }

    float o[32][4];
#pragma unroll
    for (int nt = 0; nt < 32; nt++)
#pragma unroll
        for (int e = 0; e < 4; e++) o[nt][e] = 0.f;
    float rmax0 = -1e20f, rmax1 = -1e20f, rsum0 = 0.f, rsum1 = 0.f;

    const int rmin = q0 + w * 16;
    const int rmax_w = rmin + 15;
    const int row0 = rmin + g;
    const int row1 = row0 + 8;
    const int tcol = 2 * t;

    for (int j = 0; j < ntiles; j++) {
        const int kt = kt0 + 64 * j;
        const int st = j & 1;
        const bool skipT = (kt > rmax_w) || (kt + 63 < rmin - (WIN_ - 1));
        const bool edge = !((kt + 63 <= rmin) && (kt >= rmax_w - (WIN_ - 1)));

        CP_WAIT1();            // KV_j resident (pending: KV_{j+1})
        __syncthreads();

        if (!skipT) {
            const uint32_t kByte = kBase + st * KSTG;
            const uint32_t vB = vBase + st * VSTG;
            float s[8][4];
#pragma unroll
            for (int nt = 0; nt < 8; nt++)
#pragma unroll
                for (int e = 0; e < 4; e++) s[nt][e] = 0.f;
#pragma unroll 2
            for (int ks = 0; ks < 16; ks++) {
                const uint32_t offK = (uint32_t)(((2 * ks + hiK) ^ maskK) << 4);
                uint32_t bb[4][4];
#pragma unroll
                for (int r16 = 0; r16 < 4; r16++)
                    LDSM4(bb[r16], kByte + r16 * (16 * QROWB) + offK);
#pragma unroll
                for (int nt = 0; nt < 8; nt++)
                    mma16816(s[nt], qf[ks], &bb[nt >> 1][(nt & 1) * 2]);
            }
            if (edge) {
#pragma unroll
                for (int nt = 0; nt < 8; nt++) {
                    int c0 = kt + nt * 8 + tcol, c1 = c0 + 1;
                    if (!(c0 <= row0 && c0 > row0 - WIN_)) s[nt][0] = -1e30f;
                    if (!(c1 <= row0 && c1 > row0 - WIN_)) s[nt][1] = -1e30f;
                    if (!(c0 <= row1 && c0 > row1 - WIN_)) s[nt][2] = -1e30f;
                    if (!(c1 <= row1 && c1 > row1 - WIN_)) s[nt][3] = -1e30f;
                }
            }
            float m0 = -1e30f, m1 = -1e30f;
#pragma unroll
            for (int nt = 0; nt < 8; nt++) {
                m0 = fmaxf(m0, fmaxf(s[nt][0], s[nt][1]));
                m1 = fmaxf(m1, fmaxf(s[nt][2], s[nt][3]));
            }
            m0 = fmaxf(m0, __shfl_xor_sync(0xffffffffu, m0, 1));
            m0 = fmaxf(m0, __shfl_xor_sync(0xffffffffu, m0, 2));
            m1 = fmaxf(m1, __shfl_xor_sync(0xffffffffu, m1, 1));
            m1 = fmaxf(m1, __shfl_xor_sync(0xffffffffu, m1, 2));
            float nm0 = fmaxf(rmax0, m0), nm1 = fmaxf(rmax1, m1);
            float al0 = __expf(rmax0 - nm0), al1 = __expf(rmax1 - nm1);
            float ls0 = 0.f, ls1 = 0.f;
#pragma unroll
            for (int nt = 0; nt < 8; nt++) {
                s[nt][0] = __expf(s[nt][0] - nm0);
                s[nt][1] = __expf(s[nt][1] - nm0);
                s[nt][2] = __expf(s[nt][2] - nm1);
                s[nt][3] = __expf(s[nt][3] - nm1);
                ls0 += s[nt][0] + s[nt][1];
                ls1 += s[nt][2] + s[nt][3];
            }
            ls0 += __shfl_xor_sync(0xffffffffu, ls0, 1);
            ls0 += __shfl_xor_sync(0xffffffffu, ls0, 2);
            ls1 += __shfl_xor_sync(0xffffffffu, ls1, 1);
            ls1 += __shfl_xor_sync(0xffffffffu, ls1, 2);
            rsum0 = rsum0 * al0 + ls0;
            rsum1 = rsum1 * al1 + ls1;
            rmax0 = nm0; rmax1 = nm1;
#pragma unroll
            for (int nt = 0; nt < 32; nt++) {
                o[nt][0] *= al0; o[nt][1] *= al0;
                o[nt][2] *= al1; o[nt][3] *= al1;
            }
            // PV: 4 key-chunks of 16; pack P fragments on the fly
#pragma unroll
            for (int kk = 0; kk < 4; kk++) {
                __half2 h01a = __floats2half2_rn(s[2 * kk][0], s[2 * kk][1]);
                __half2 h23a = __floats2half2_rn(s[2 * kk][2], s[2 * kk][3]);
                __half2 h01b = __floats2half2_rn(s[2 * kk + 1][0], s[2 * kk + 1][1]);
                __half2 h23b = __floats2half2_rn(s[2 * kk + 1][2], s[2 * kk + 1][3]);
                uint32_t Ah[4] = {*(uint32_t*)&h01a, *(uint32_t*)&h23a,
                                  *(uint32_t*)&h01b, *(uint32_t*)&h23b};
#pragma unroll
                for (int p = 0; p < 16; p++) {
                    uint32_t rv[4];
                    LDSM4(rv, vB + p * (16 * VLD * 2) + kk * 32);
                    mma16816(o[2 * p], Ah, &rv[0]);
                    mma16816(o[2 * p + 1], Ah, &rv[2]);
                }
            }
        }
        __syncthreads();       // all warps done with stage st
        int lj = j + 2;
        if (lj < ntiles) LOAD_KV(kt0 + 64 * lj, lj & 1);
        CP_COMMIT();           // always commit to keep group count uniform
    }

    // epilogue: normalize and write fp16 directly into A2
    float inv0 = 1.0f / rsum0, inv1 = 1.0f / rsum1;
    __half* d0p = A2out + (size_t)(b * S_ + row0) * GK_ + h * HD_;
    __half* d1p = A2out + (size_t)(b * S_ + row1) * GK_ + h * HD_;
#pragma unroll
    for (int nt = 0; nt < 32; nt++) {
        int d = nt * 8 + tcol;
        __half2 v0 = __floats2half2_rn(o[nt][0] * inv0, o[nt][1] * inv0);
        __half2 v1 = __floats2half2_rn(o[nt][2] * inv1, o[nt][3] * inv1);
        *(__half2*)(d0p + d) = v0;
        *(__half2*)(d1p + d) = v1;
    }
#undef LOAD_KV
}

// ---------------------------------------------------------------------------
// Launch
// ---------------------------------------------------------------------------
extern "C" void kernel_launch(void* const* d_in, const int* in_sizes, int n_in,
                              void* d_out, int out_size)
{
    const float* hidden    = (const float*)d_in[0];
    const int*   positions = (const int*)d_in[1];
    const float* Wq        = (const float*)d_in[2];
    const float* bq        = (const float*)d_in[3];
    const float* Wk        = (const float*)d_in[4];
    const float* bk        = (const float*)d_in[5];
    const float* Wv        = (const float*)d_in[6];
    const float* bv        = (const float*)d_in[7];
    const float* Wo        = (const float*)d_in[8];
    float* out = (float*)d_out;

    float *qkv, *b4;
    float2* rt;
    __half *a2, *w2, *q2, *k2, *vt;
    cudaGetSymbolAddress((void**)&qkv, g_qkv);
    cudaGetSymbolAddress((void**)&b4, g_bias4);
    cudaGetSymbolAddress((void**)&a2, g_a2);
    cudaGetSymbolAddress((void**)&w2, g_w2);
    cudaGetSymbolAddress((void**)&rt, g_rope);
    cudaGetSymbolAddress((void**)&q2, g_q2);
    cudaGetSymbolAddress((void**)&k2, g_k2);
    cudaGetSymbolAddress((void**)&vt, g_vt);

    const int M = B_ * S_;
    const size_t gemm_smem = (size_t)2 * NSTAGE * STGB + 512;   // 98,816 B
    cudaFuncSetAttribute(gemm_mma, cudaFuncAttributeMaxDynamicSharedMemorySize, (int)gemm_smem);

    // fused rope table + bias concat
    rope_bias<<<(B_ * S_ * 128) / 256 + 16, 256>>>(positions, rt, bq, bk, bv, b4);
    convA2<<<M * 512 / 256, 256>>>(hidden, a2);

    // merged Q|K|V weight conversion + projection (N=4096)
    convW3<<<dim3(128, 64), 256>>>(Wq, Wk, Wv, w2);
    gemm_mma<<<dim3(32, 64), 128, gemm_smem>>>(a2, w2, b4, qkv, 4096);

    // merged RoPE-Q/K + V-transpose conversion
    conv_qkv<<<NQKBLK + 8192, 256>>>(qkv, rt, q2, k2, vt);

    // attention writes fp16 directly into A2
    {
        size_t smem = (size_t)(128 * QROWB + 2 * KSTG + 2 * VSTG);  // 204,800 B
        cudaFuncSetAttribute(attn_mma, cudaFuncAttributeMaxDynamicSharedMemorySize, (int)smem);
        attn_mma<<<dim3(S_ / 128, NH_, B_), 256, smem>>>(q2, k2, vt, a2);
    }

    // O projection
    convW2<<<dim3(2048 / 32, 64), 256>>>(Wo, w2, 2048);
    gemm_mma<<<dim3(16, 64), 128, gemm_smem>>>(a2, w2, nullptr, out, 2048);
}